// round 16
// baseline (speedup 1.0000x reference)
#include <cuda_runtime.h>

#define NROWS 8192
#define D     4096
#define NT    64
#define PER   64    // elements per thread; 6 reg bits per layout, 2 layouts = 12 bits
#define GRID  1184  // 148 SMs x 8 CTAs, persistent

// g permuted into layout-B'' order, packed float4:
// g4[jq*64 + t].c = g[(t&3) + 4*(4*jq+c) + 256*(t>>2)],  g = g_mu + softplus(g_rho)*eps
__device__ float4 g4[D / 4];

__global__ void prep_g_kernel(const float* __restrict__ g_mu,
                              const float* __restrict__ g_rho,
                              const float* __restrict__ eps) {
    int u = blockIdx.x * blockDim.x + threadIdx.x;   // [0, 1024)
    if (u < D / 4) {
        int t  = u & 63;
        int jq = u >> 6;
        float4 o;
        float* op = (float*)&o;
#pragma unroll
        for (int c = 0; c < 4; c++) {
            int j = 4 * jq + c;
            int i = (t & 3) + 4 * j + 256 * (t >> 2);
            float x  = g_rho[i];
            float sp = fmaxf(x, 0.0f) + log1pf(expf(-fabsf(x)));
            op[c] = g_mu[i] + sp * eps[i];
        }
        g4[u] = o;
    }
}

// SMEM swizzle: bijection on [0,4096). Bits 2-4 ^= bits 8-10.
//  A'-side 128-bit (word = 256k+4t): 16B-group bits = t0t1t2 ^ k0k1k2(const) -> 8 distinct/phase.
//  B''-side scalar (word = t01 + 4j + 256*t[2:6]): bank = (t0,t1,j0^t2,j1^t3,j2^t4) -> 32 distinct.
__device__ __forceinline__ int sw(int i) {
    return i ^ (((i >> 8) & 7) << 2);
}

// ---- packed f32x2 primitives ----
__device__ __forceinline__ void bf_pair(float* r, int a, int b, unsigned long long neg1) {
    float ax = r[a], ay = r[a + 1], bx = r[b], by = r[b + 1];
    asm("{\n\t"
        ".reg .b64 ra, rb, rs, rd;\n\t"
        "mov.b64 ra, {%4,%5};\n\t"
        "mov.b64 rb, {%6,%7};\n\t"
        "add.rn.f32x2 rs, ra, rb;\n\t"
        "fma.rn.f32x2 rd, rb, %8, ra;\n\t"
        "mov.b64 {%0,%1}, rs;\n\t"
        "mov.b64 {%2,%3}, rd;\n\t"
        "}"
        : "=f"(r[a]), "=f"(r[a + 1]), "=f"(r[b]), "=f"(r[b + 1])
        : "f"(ax), "f"(ay), "f"(bx), "f"(by), "l"(neg1));
}

__device__ __forceinline__ void pk_mul2(float& ox, float& oy,
                                        float ax, float ay, float bx, float by) {
    asm("{\n\t"
        ".reg .b64 ra, rb, rd;\n\t"
        "mov.b64 ra, {%2,%3};\n\t"
        "mov.b64 rb, {%4,%5};\n\t"
        "mul.rn.f32x2 rd, ra, rb;\n\t"
        "mov.b64 {%0,%1}, rd;\n\t"
        "}"
        : "=f"(ox), "=f"(oy) : "f"(ax), "f"(ay), "f"(bx), "f"(by));
}

__device__ __forceinline__ void prefetch_l2(const void* p) {
    asm volatile("prefetch.global.L2 [%0];" :: "l"(p));
}

// Six FWHT stages over the 6 register-index bits of r[64].
// Reg bit 0: scalar intra-pair stage. Reg bits 1-5: packed across pairs.
__device__ __forceinline__ void six_stages(float* r, unsigned long long neg1) {
#pragma unroll
    for (int m = 0; m < 32; m++) {
        float a = r[2 * m], b = r[2 * m + 1];
        r[2 * m]     = a + b;
        r[2 * m + 1] = a - b;
    }
#pragma unroll
    for (int pb = 1; pb <= 16; pb <<= 1) {
#pragma unroll
        for (int m = 0; m < 32; m++) {
            if (!(m & pb)) bf_pair(r, 2 * m, 2 * (m | pb), neg1);
        }
    }
}

__global__ __launch_bounds__(NT, 8) void whvi_kernel(const float* __restrict__ x,
                                                     const float* __restrict__ s1,
                                                     const float* __restrict__ s2,
                                                     float* __restrict__ out) {
    __shared__ float sm[D];   // 16KB transpose scratch

    const unsigned long long NEG1 = 0xBF800000BF800000ULL;  // (-1.0f, -1.0f)

    const int t = threadIdx.x;                     // 6 bits
    const int bB = (t & 3) + 256 * (t >> 2);       // B'' base: i = bB + 4j
    const float4* __restrict__ s2v = (const float4*)s2;
    const float4* __restrict__ s1v = (const float4*)s1;

    float r[PER];

    for (int row = blockIdx.x; row < NROWS; row += GRID) {
        const size_t rowoff = (size_t)row * D;
        const float4* __restrict__ x4 = (const float4*)(x + rowoff);
        float4* __restrict__ o4       = (float4*)(out + rowoff);

        // ---- Load layout A' (r[4k+c] = i = 256k+4t+c): coalesced float4, fused *s2 ----
#pragma unroll
        for (int k = 0; k < 16; k++) {
            float4 v = x4[64 * k + t];
            float4 s = __ldg(&s2v[64 * k + t]);
            pk_mul2(r[4 * k + 0], r[4 * k + 1], v.x, v.y, s.x, s.y);
            pk_mul2(r[4 * k + 2], r[4 * k + 3], v.z, v.w, s.z, s.w);
        }

        // ---- Prefetch next row's x into L2 (overlaps with this row's compute) ----
        if (row + GRID < NROWS) {
            const float* xn = x + rowoff + (size_t)GRID * D;
            prefetch_l2(xn + 64 * t);        // 128B line 2t
            prefetch_l2(xn + 64 * t + 32);   // 128B line 2t+1
        }

        // FWHT#1 part 1: i-bits {0,1,8,9,10,11} (layout A')
        six_stages(r, NEG1);

        // T1: A' -> B''  (write 128-bit, read scalar)
        __syncthreads();                     // prev iteration's T2 reads done
#pragma unroll
        for (int k = 0; k < 16; k++) {
            float4 v = make_float4(r[4 * k], r[4 * k + 1], r[4 * k + 2], r[4 * k + 3]);
            *(float4*)&sm[sw(256 * k + 4 * t)] = v;          // STS.128
        }
        __syncthreads();
#pragma unroll
        for (int j = 0; j < PER; j++)
            r[j] = sm[sw(bB + 4 * j)];                       // LDS.32

        // FWHT#1 part 2: i-bits {2..7} (layout B'')
        six_stages(r, NEG1);

        // ---- elementwise * g (layout B'', pre-permuted, coalesced float4) ----
#pragma unroll
        for (int jq = 0; jq < 16; jq++) {
            float4 gv = g4[jq * 64 + t];
            pk_mul2(r[4 * jq + 0], r[4 * jq + 1], r[4 * jq + 0], r[4 * jq + 1], gv.x, gv.y);
            pk_mul2(r[4 * jq + 2], r[4 * jq + 3], r[4 * jq + 2], r[4 * jq + 3], gv.z, gv.w);
        }

        // FWHT#2 part 1: i-bits {2..7} (layout B'')
        six_stages(r, NEG1);

        // T2: B'' -> A'  (write scalar, read 128-bit)
        __syncthreads();                     // all T1 reads done
#pragma unroll
        for (int j = 0; j < PER; j++)
            sm[sw(bB + 4 * j)] = r[j];                       // STS.32
        __syncthreads();
#pragma unroll
        for (int k = 0; k < 16; k++) {
            float4 v = *(const float4*)&sm[sw(256 * k + 4 * t)];  // LDS.128
            r[4 * k + 0] = v.x; r[4 * k + 1] = v.y;
            r[4 * k + 2] = v.z; r[4 * k + 3] = v.w;
        }

        // FWHT#2 part 2: i-bits {0,1,8,9,10,11} (layout A')
        six_stages(r, NEG1);

        // ---- Store layout A': coalesced float4, fused *s1 ----
#pragma unroll
        for (int k = 0; k < 16; k++) {
            float4 s = __ldg(&s1v[64 * k + t]);
            float4 v;
            pk_mul2(v.x, v.y, r[4 * k + 0], r[4 * k + 1], s.x, s.y);
            pk_mul2(v.z, v.w, r[4 * k + 2], r[4 * k + 3], s.z, s.w);
            o4[64 * k + t] = v;
        }
    }
}

extern "C" void kernel_launch(void* const* d_in, const int* in_sizes, int n_in,
                              void* d_out, int out_size) {
    const float* x     = (const float*)d_in[0];
    const float* s1    = (const float*)d_in[1];
    const float* s2    = (const float*)d_in[2];
    const float* g_mu  = (const float*)d_in[3];
    const float* g_rho = (const float*)d_in[4];
    const float* eps   = (const float*)d_in[5];
    float* out = (float*)d_out;

    prep_g_kernel<<<(D / 4 + 255) / 256, 256>>>(g_mu, g_rho, eps);
    whvi_kernel<<<GRID, NT>>>(x, s1, s2, out);
}